// round 5
// baseline (speedup 1.0000x reference)
#include <cuda_runtime.h>
#include <cuda_bf16.h>

// Problem dims
#define BB 32
#define TT 512
#define DD 512
#define EE 8
#define HH 2048

// GEMM tile config
#define BM 128
#define BN 128
#define BK 32

// ---------------- device scratch (no allocations allowed) ----------------
__device__ __nv_bfloat16 g_xhi[(size_t)BB*TT*DD];
__device__ __nv_bfloat16 g_xlo[(size_t)BB*TT*DD];
__device__ __nv_bfloat16 g_w1hi[(size_t)EE*DD*HH];
__device__ __nv_bfloat16 g_w1lo[(size_t)EE*DD*HH];
__device__ __nv_bfloat16 g_w2hi[(size_t)EE*HH*DD];
__device__ __nv_bfloat16 g_w2lo[(size_t)EE*HH*DD];
__device__ __nv_bfloat16 g_hhi[(size_t)BB*TT*HH];
__device__ __nv_bfloat16 g_hlo[(size_t)BB*TT*HH];
__device__ float g_pool_part[BB*4*DD];
__device__ int   g_chosen_d[BB];

// ---------------- helpers ----------------
__device__ __forceinline__ void split2(float v, __nv_bfloat16& hi, __nv_bfloat16& lo) {
    hi = __float2bfloat16(v);
    lo = __float2bfloat16(v - __bfloat162float(hi));
}

__device__ __forceinline__ void mma16816(float c[4],
                                         const unsigned a[4],
                                         const unsigned b[2]) {
    asm volatile(
        "mma.sync.aligned.m16n8k16.row.col.f32.bf16.bf16.f32 "
        "{%0,%1,%2,%3},{%4,%5,%6,%7},{%8,%9},{%0,%1,%2,%3};\n"
        : "+f"(c[0]), "+f"(c[1]), "+f"(c[2]), "+f"(c[3])
        : "r"(a[0]), "r"(a[1]), "r"(a[2]), "r"(a[3]), "r"(b[0]), "r"(b[1]));
}

// ---------------- split fp32 -> bf16 hi/lo ----------------
__global__ void split_kernel(const float* __restrict__ in, int which) {
    __nv_bfloat16 *hi, *lo;
    if (which == 0)      { hi = g_xhi;  lo = g_xlo;  }
    else if (which == 1) { hi = g_w1hi; lo = g_w1lo; }
    else                 { hi = g_w2hi; lo = g_w2lo; }
    const size_t n = 8388608;  // all three are 8.39M elements
    for (size_t i = (size_t)blockIdx.x * blockDim.x + threadIdx.x; i < n;
         i += (size_t)gridDim.x * blockDim.x) {
        float v = in[i];
        __nv_bfloat16 h, l;
        split2(v, h, l);
        hi[i] = h;
        lo[i] = l;
    }
}

// ---------------- pooling partials: sum over 128 tokens per (b, s) ----------------
__global__ void pool_kernel(const float* __restrict__ x) {
    int b = blockIdx.x, s = blockIdx.y, d = threadIdx.x;  // 512 threads
    const float* xb = x + ((size_t)b * TT + (size_t)s * 128) * DD + d;
    float acc = 0.f;
#pragma unroll 8
    for (int t = 0; t < 128; t++) acc += xb[(size_t)t * DD];
    g_pool_part[(b * 4 + s) * DD + d] = acc;
}

// ---------------- router: logits, softmax, argmax ----------------
__global__ void router_kernel(const float* __restrict__ Wp, const float* __restrict__ bp,
                              float* __restrict__ out, int out_size) {
    __shared__ float s_logit[BB][EE];
    int tid = threadIdx.x;           // 256 threads: (b, e) pairs
    int b = tid >> 3, e = tid & 7;
    const float* P = g_pool_part + (size_t)b * 4 * DD;
    float acc = bp[e];
    for (int d = 0; d < DD; d++) {
        float p = (P[d] + P[DD + d] + P[2 * DD + d] + P[3 * DD + d]) * (1.f / (float)TT);
        acc += p * Wp[d * EE + e];
    }
    s_logit[b][e] = acc;
    __syncthreads();
    if (tid < BB) {
        int bb = tid;
        float mx = s_logit[bb][0];
        int arg = 0;
        for (int k = 1; k < EE; k++)
            if (s_logit[bb][k] > mx) { mx = s_logit[bb][k]; arg = k; }
        float ex[EE], sum = 0.f;
        for (int k = 0; k < EE; k++) { ex[k] = expf(s_logit[bb][k] - mx); sum += ex[k]; }
        g_chosen_d[bb] = arg;
        if (out_size >= BB * TT * DD + BB * EE + BB) {
            float inv = 1.f / sum;
            for (int k = 0; k < EE; k++) out[BB * TT * DD + bb * EE + k] = ex[k] * inv;
            out[BB * TT * DD + BB * EE + bb] = (float)arg;
        }
    }
}

// ---------------- fused-precision GEMM (bf16 hi/lo x3 MMA, fp32 accum) ----------
// MODE 0: h = relu(x @ W1[e] + b1[e])   [M=T=512, N=H=2048, K=D=512] -> hi/lo scratch
// MODE 1: out = h @ W2[e] + b2[e]       [M=T=512, N=D=512,  K=H=2048] -> fp32 d_out
template <int MODE>
__global__ void __launch_bounds__(256) ffn_gemm(const float* __restrict__ bias,
                                                float* __restrict__ out) {
    constexpr int K = (MODE == 0) ? DD : HH;
    constexpr int N = (MODE == 0) ? HH : DD;

    const int b = blockIdx.z;
    const int e = g_chosen_d[b];
    const int m0 = blockIdx.y * BM;
    const int n0 = blockIdx.x * BN;

    const __nv_bfloat16* __restrict__ Ahi =
        (MODE == 0) ? (g_xhi + (size_t)b * TT * DD) : (g_hhi + (size_t)b * TT * HH);
    const __nv_bfloat16* __restrict__ Alo =
        (MODE == 0) ? (g_xlo + (size_t)b * TT * DD) : (g_hlo + (size_t)b * TT * HH);
    const __nv_bfloat16* __restrict__ Bhi =
        (MODE == 0) ? (g_w1hi + (size_t)e * DD * HH) : (g_w2hi + (size_t)e * HH * DD);
    const __nv_bfloat16* __restrict__ Blo =
        (MODE == 0) ? (g_w1lo + (size_t)e * DD * HH) : (g_w2lo + (size_t)e * HH * DD);

    __shared__ __nv_bfloat16 sAhi[BM][BK + 2];
    __shared__ __nv_bfloat16 sAlo[BM][BK + 2];
    __shared__ __nv_bfloat16 sBhi[BK][BN + 8];
    __shared__ __nv_bfloat16 sBlo[BK][BN + 8];

    const int tid  = threadIdx.x;
    const int lane = tid & 31;
    const int warp = tid >> 5;
    const int wm = (warp >> 2) * 64;   // 2 warps along M
    const int wn = (warp & 3) * 32;    // 4 warps along N
    const int group = lane >> 2;       // 0..7
    const int tig   = lane & 3;        // 0..3

    float acc[4][4][4];
#pragma unroll
    for (int mt = 0; mt < 4; mt++)
#pragma unroll
        for (int nt = 0; nt < 4; nt++)
#pragma unroll
            for (int i = 0; i < 4; i++) acc[mt][nt][i] = 0.f;

    for (int k0 = 0; k0 < K; k0 += BK) {
        // load A tile (128x32) as 32-bit chunks (2 bf16 each)
#pragma unroll
        for (int i = tid; i < BM * BK / 2; i += 256) {
            int r = i >> 4, c2 = i & 15;
            size_t gi = (size_t)(m0 + r) * K + k0 + (c2 << 1);
            *(unsigned*)&sAhi[r][c2 << 1] = *(const unsigned*)&Ahi[gi];
            *(unsigned*)&sAlo[r][c2 << 1] = *(const unsigned*)&Alo[gi];
        }
        // load B tile (32x128)
#pragma unroll
        for (int i = tid; i < BK * BN / 2; i += 256) {
            int r = i >> 6, c2 = i & 63;
            size_t gi = (size_t)(k0 + r) * N + n0 + (c2 << 1);
            *(unsigned*)&sBhi[r][c2 << 1] = *(const unsigned*)&Bhi[gi];
            *(unsigned*)&sBlo[r][c2 << 1] = *(const unsigned*)&Blo[gi];
        }
        __syncthreads();

#pragma unroll
        for (int ks = 0; ks < 2; ks++) {
            const int kb = ks * 16;
            unsigned ah[4][4], al[4][4], bh[4][2], bl[4][2];
#pragma unroll
            for (int mt = 0; mt < 4; mt++) {
                int r = wm + mt * 16 + group;
                int kc = kb + tig * 2;
                ah[mt][0] = *(const unsigned*)&sAhi[r][kc];
                ah[mt][1] = *(const unsigned*)&sAhi[r + 8][kc];
                ah[mt][2] = *(const unsigned*)&sAhi[r][kc + 8];
                ah[mt][3] = *(const unsigned*)&sAhi[r + 8][kc + 8];
                al[mt][0] = *(const unsigned*)&sAlo[r][kc];
                al[mt][1] = *(const unsigned*)&sAlo[r + 8][kc];
                al[mt][2] = *(const unsigned*)&sAlo[r][kc + 8];
                al[mt][3] = *(const unsigned*)&sAlo[r + 8][kc + 8];
            }
#pragma unroll
            for (int nt = 0; nt < 4; nt++) {
                int c = wn + nt * 8 + group;
                int kr = kb + tig * 2;
                bh[nt][0] = (unsigned)(*(const unsigned short*)&sBhi[kr][c]) |
                            ((unsigned)(*(const unsigned short*)&sBhi[kr + 1][c]) << 16);
                bh[nt][1] = (unsigned)(*(const unsigned short*)&sBhi[kr + 8][c]) |
                            ((unsigned)(*(const unsigned short*)&sBhi[kr + 9][c]) << 16);
                bl[nt][0] = (unsigned)(*(const unsigned short*)&sBlo[kr][c]) |
                            ((unsigned)(*(const unsigned short*)&sBlo[kr + 1][c]) << 16);
                bl[nt][1] = (unsigned)(*(const unsigned short*)&sBlo[kr + 8][c]) |
                            ((unsigned)(*(const unsigned short*)&sBlo[kr + 9][c]) << 16);
            }
#pragma unroll
            for (int mt = 0; mt < 4; mt++) {
#pragma unroll
                for (int nt = 0; nt < 4; nt++) {
                    mma16816(acc[mt][nt], ah[mt], bh[nt]);  // hi*hi
                    mma16816(acc[mt][nt], ah[mt], bl[nt]);  // hi*lo
                    mma16816(acc[mt][nt], al[mt], bh[nt]);  // lo*hi
                }
            }
        }
        __syncthreads();
    }

    // -------- epilogue --------
#pragma unroll
    for (int mt = 0; mt < 4; mt++) {
        int r0 = m0 + wm + mt * 16 + group;
#pragma unroll
        for (int nt = 0; nt < 4; nt++) {
            int c = n0 + wn + nt * 8 + tig * 2;
            float v0 = acc[mt][nt][0], v1 = acc[mt][nt][1];
            float v2 = acc[mt][nt][2], v3 = acc[mt][nt][3];
            if (MODE == 0) {
                float bb0 = bias[e * HH + c], bb1 = bias[e * HH + c + 1];
                v0 = fmaxf(v0 + bb0, 0.f);
                v1 = fmaxf(v1 + bb1, 0.f);
                v2 = fmaxf(v2 + bb0, 0.f);
                v3 = fmaxf(v3 + bb1, 0.f);
                __nv_bfloat16 h0, h1, h2, h3, l0, l1, l2, l3;
                split2(v0, h0, l0); split2(v1, h1, l1);
                split2(v2, h2, l2); split2(v3, h3, l3);
                size_t base = (size_t)b * TT * HH;
                size_t i0 = base + (size_t)r0 * HH + c;
                size_t i8 = base + (size_t)(r0 + 8) * HH + c;
                *(__nv_bfloat162*)&g_hhi[i0] = __halves2bfloat162(h0, h1);
                *(__nv_bfloat162*)&g_hlo[i0] = __halves2bfloat162(l0, l1);
                *(__nv_bfloat162*)&g_hhi[i8] = __halves2bfloat162(h2, h3);
                *(__nv_bfloat162*)&g_hlo[i8] = __halves2bfloat162(l2, l3);
            } else {
                float bb0 = bias[e * DD + c], bb1 = bias[e * DD + c + 1];
                size_t base = (size_t)b * TT * DD;
                float2 p0 = make_float2(v0 + bb0, v1 + bb1);
                float2 p1 = make_float2(v2 + bb0, v3 + bb1);
                *(float2*)&out[base + (size_t)r0 * DD + c] = p0;
                *(float2*)&out[base + (size_t)(r0 + 8) * DD + c] = p1;
            }
        }
    }
}

// ---------------- launch ----------------
extern "C" void kernel_launch(void* const* d_in, const int* in_sizes, int n_in,
                              void* d_out, int out_size) {
    const float* x  = (const float*)d_in[0];
    const float* Wp = (const float*)d_in[1];
    const float* bp = (const float*)d_in[2];
    const float* W1 = (const float*)d_in[3];
    const float* b1 = (const float*)d_in[4];
    const float* W2 = (const float*)d_in[5];
    const float* b2 = (const float*)d_in[6];
    float* out = (float*)d_out;
    (void)in_sizes; (void)n_in;

    split_kernel<<<4096, 256>>>(x, 0);
    split_kernel<<<4096, 256>>>(W1, 1);
    split_kernel<<<4096, 256>>>(W2, 2);
    pool_kernel<<<dim3(BB, 4), DD>>>(x);
    router_kernel<<<1, 256>>>(Wp, bp, out, out_size);

    // GEMM1: [512 x 2048] per batch, K=512
    ffn_gemm<0><<<dim3(HH / BN, TT / BM, BB), 256>>>(b1, out);
    // GEMM2: [512 x 512] per batch, K=2048
    ffn_gemm<1><<<dim3(DD / BN, TT / BM, BB), 256>>>(b2, out);
}

// round 9
// speedup vs baseline: 1.5732x; 1.5732x over previous
#include <cuda_runtime.h>
#include <cuda_bf16.h>
#include <cstdint>

// Problem dims
#define BB 32
#define TT 512
#define DD 512
#define EE 8
#define HH 2048

// GEMM tile config
#define TM 128
#define TN 128
#define BK 64   // K per smem stage (128B rows -> SW128 swizzle)

// ---------------- device scratch (no allocations allowed) ----------------
__device__ __nv_bfloat16 g_xhi[(size_t)BB*TT*DD];
__device__ __nv_bfloat16 g_xlo[(size_t)BB*TT*DD];
__device__ __nv_bfloat16 g_w1hi[(size_t)EE*HH*DD];  // transposed: [E][H][D]
__device__ __nv_bfloat16 g_w1lo[(size_t)EE*HH*DD];
__device__ __nv_bfloat16 g_w2hi[(size_t)EE*DD*HH];  // transposed: [E][D][H]
__device__ __nv_bfloat16 g_w2lo[(size_t)EE*DD*HH];
__device__ __nv_bfloat16 g_hhi[(size_t)BB*TT*HH];
__device__ __nv_bfloat16 g_hlo[(size_t)BB*TT*HH];
__device__ float g_pool_part[BB*4*DD];
__device__ int   g_chosen_d[BB];

// ---------------- helpers ----------------
__device__ __forceinline__ void split2(float v, __nv_bfloat16& hi, __nv_bfloat16& lo) {
    hi = __float2bfloat16(v);
    lo = __float2bfloat16(v - __bfloat162float(hi));
}
__device__ __forceinline__ uint32_t s2u(const void* p) {
    uint32_t a;
    asm("{ .reg .u64 t; cvta.to.shared.u64 t, %1; cvt.u32.u64 %0, t; }" : "=r"(a) : "l"(p));
    return a;
}
__device__ __forceinline__ void cp16(uint32_t dst, const void* src) {
    asm volatile("cp.async.cg.shared.global [%0], [%1], 16;" :: "r"(dst), "l"(src));
}
__device__ __forceinline__ void mma16816(float c[4], const unsigned a[4],
                                         unsigned b0, unsigned b1) {
    asm volatile(
        "mma.sync.aligned.m16n8k16.row.col.f32.bf16.bf16.f32 "
        "{%0,%1,%2,%3},{%4,%5,%6,%7},{%8,%9},{%0,%1,%2,%3};\n"
        : "+f"(c[0]), "+f"(c[1]), "+f"(c[2]), "+f"(c[3])
        : "r"(a[0]), "r"(a[1]), "r"(a[2]), "r"(a[3]), "r"(b0), "r"(b1));
}
__device__ __forceinline__ void ldm4(unsigned r[4], uint32_t a) {
    asm volatile("ldmatrix.sync.aligned.m8n8.x4.shared.b16 {%0,%1,%2,%3}, [%4];"
                 : "=r"(r[0]), "=r"(r[1]), "=r"(r[2]), "=r"(r[3]) : "r"(a));
}

// ---------------- split x: fp32 -> bf16 hi/lo ----------------
__global__ void xsplit_kernel(const float* __restrict__ x) {
    size_t n = (size_t)BB * TT * DD;
    for (size_t i = (size_t)blockIdx.x * blockDim.x + threadIdx.x; i < n;
         i += (size_t)gridDim.x * blockDim.x) {
        __nv_bfloat16 h, l;
        split2(x[i], h, l);
        g_xhi[i] = h;
        g_xlo[i] = l;
    }
}

// ---------------- transpose + split weights: [E][R][C] fp32 -> [E][C][R] bf16 hi/lo ----
__global__ void tsplit_kernel(const float* __restrict__ in, int which, int R, int C) {
    __shared__ float t[32][33];
    __nv_bfloat16* hi = which ? g_w2hi : g_w1hi;
    __nv_bfloat16* lo = which ? g_w2lo : g_w1lo;
    int e = blockIdx.z;
    const float* src = in + (size_t)e * R * C;
    __nv_bfloat16* H = hi + (size_t)e * R * C;
    __nv_bfloat16* L = lo + (size_t)e * R * C;
    int c0 = blockIdx.x * 32, r0 = blockIdx.y * 32;
    int tx = threadIdx.x, ty = threadIdx.y;  // block (32, 8)
#pragma unroll
    for (int i = ty; i < 32; i += 8)
        t[i][tx] = src[(size_t)(r0 + i) * C + c0 + tx];
    __syncthreads();
#pragma unroll
    for (int i = ty; i < 32; i += 8) {
        float v = t[tx][i];
        __nv_bfloat16 h, l;
        split2(v, h, l);
        H[(size_t)(c0 + i) * R + r0 + tx] = h;
        L[(size_t)(c0 + i) * R + r0 + tx] = l;
    }
}

// ---------------- pooling partials ----------------
__global__ void pool_kernel(const float* __restrict__ x) {
    int b = blockIdx.x, s = blockIdx.y, d = threadIdx.x;  // 512 threads
    const float* xb = x + ((size_t)b * TT + (size_t)s * 128) * DD + d;
    float acc = 0.f;
#pragma unroll 8
    for (int t = 0; t < 128; t++) acc += xb[(size_t)t * DD];
    g_pool_part[(b * 4 + s) * DD + d] = acc;
}

// ---------------- router ----------------
__global__ void router_kernel(const float* __restrict__ Wp, const float* __restrict__ bp,
                              float* __restrict__ out, int out_size) {
    __shared__ float s_logit[BB][EE];
    int tid = threadIdx.x;  // 256 threads: (b, e) pairs
    int b = tid >> 3, e = tid & 7;
    const float* P = g_pool_part + (size_t)b * 4 * DD;
    float acc = bp[e];
    for (int d = 0; d < DD; d++) {
        float p = (P[d] + P[DD + d] + P[2 * DD + d] + P[3 * DD + d]) * (1.f / (float)TT);
        acc += p * Wp[d * EE + e];
    }
    s_logit[b][e] = acc;
    __syncthreads();
    if (tid < BB) {
        int bb = tid;
        float mx = s_logit[bb][0];
        int arg = 0;
        for (int k = 1; k < EE; k++)
            if (s_logit[bb][k] > mx) { mx = s_logit[bb][k]; arg = k; }
        float ex[EE], sum = 0.f;
        for (int k = 0; k < EE; k++) { ex[k] = expf(s_logit[bb][k] - mx); sum += ex[k]; }
        g_chosen_d[bb] = arg;
        if (out_size >= BB * TT * DD + BB * EE + BB) {
            float inv = 1.f / sum;
            for (int k = 0; k < EE; k++) out[BB * TT * DD + bb * EE + k] = ex[k] * inv;
            out[BB * TT * DD + BB * EE + bb] = (float)arg;
        }
    }
}

// ---------------- pipelined HMMA GEMM (bf16 hi/lo x3 passes, fp32 accum) ------
// smem: 2 stages x 4 tiles (Ahi, Alo, Bhi, Blo), each tile 128 rows x 128B, SW128.
//   stage s, tile t at: s*65536 + t*16384
#define STAGE_BYTES 65536
#define TILE_BYTES  16384
#define SMEM_BYTES  (2 * STAGE_BYTES)

template <int K>
__device__ __forceinline__ void load_stage(uint32_t sb, int tid, int it,
                                           const __nv_bfloat16* Ahi, const __nv_bfloat16* Alo,
                                           const __nv_bfloat16* Bhi, const __nv_bfloat16* Blo,
                                           int m0, int n0) {
    int s = it & 1, k0 = it * BK;
    const __nv_bfloat16* srcs[4] = {Ahi + (size_t)m0 * K, Alo + (size_t)m0 * K,
                                    Bhi + (size_t)n0 * K, Blo + (size_t)n0 * K};
#pragma unroll
    for (int t = 0; t < 4; t++) {
        uint32_t base = sb + (uint32_t)s * STAGE_BYTES + (uint32_t)t * TILE_BYTES;
        const char* g = (const char*)srcs[t] + (size_t)k0 * 2;
#pragma unroll
        for (int i = 0; i < 4; i++) {
            int idx = tid + i * 256;          // 1024 chunks of 16B per tile
            int r = idx >> 3, c = idx & 7;
            uint32_t off = (uint32_t)(r * 128 + c * 16);
            cp16(base + (off ^ ((off >> 3) & 0x70)), g + (size_t)r * (K * 2) + c * 16);
        }
    }
    asm volatile("cp.async.commit_group;" ::: "memory");
}

// MODE 0: h = relu(x @ W1t^T + b1)  [M=512, N=2048, K=512]  -> bf16 hi/lo scratch
// MODE 1: out = h @ W2t^T + b2      [M=512, N=512,  K=2048] -> fp32 d_out
template <int MODE>
__global__ void __launch_bounds__(256) ffn_gemm(const float* __restrict__ bias,
                                                float* __restrict__ out) {
    constexpr int K = (MODE == 0) ? DD : HH;
    constexpr int NK = K / BK;
    extern __shared__ char smem[];
    uint32_t sb = s2u(smem);
    const int tid = threadIdx.x, wid = tid >> 5, lane = tid & 31;
    const int b = blockIdx.z, m0 = blockIdx.y * TM, n0 = blockIdx.x * TN;
    const int e = g_chosen_d[b];
    const int wm = (wid >> 2) * 64;   // 2 warps along M
    const int wn = (wid & 3) * 32;    // 4 warps along N

    const __nv_bfloat16 *Ahi, *Alo, *Bhi, *Blo;
    if (MODE == 0) {
        Ahi = g_xhi + (size_t)b * TT * DD;  Alo = g_xlo + (size_t)b * TT * DD;
        Bhi = g_w1hi + (size_t)e * HH * DD; Blo = g_w1lo + (size_t)e * HH * DD;
    } else {
        Ahi = g_hhi + (size_t)b * TT * HH;  Alo = g_hlo + (size_t)b * TT * HH;
        Bhi = g_w2hi + (size_t)e * DD * HH; Blo = g_w2lo + (size_t)e * DD * HH;
    }

    // per-thread ldmatrix row addressing (row fixed per tile; only k-offset varies)
    const int colpart = (lane >> 4) << 4;      // 0 or 16 bytes (k8..15 half)
    uint32_t aBase[4], aXor[4], bBase[2], bXor[2];
#pragma unroll
    for (int mt = 0; mt < 4; mt++) {
        int r = wm + mt * 16 + (lane & 15);
        aBase[mt] = (uint32_t)(r * 128);
        aXor[mt]  = (uint32_t)((r & 7) << 4);
    }
#pragma unroll
    for (int np = 0; np < 2; np++) {
        int r = wn + np * 16 + (lane & 15);
        bBase[np] = (uint32_t)(r * 128);
        bXor[np]  = (uint32_t)((r & 7) << 4);
    }

    float acc[4][4][4];
#pragma unroll
    for (int mt = 0; mt < 4; mt++)
#pragma unroll
        for (int nt = 0; nt < 4; nt++)
#pragma unroll
            for (int i = 0; i < 4; i++) acc[mt][nt][i] = 0.f;

    load_stage<K>(sb, tid, 0, Ahi, Alo, Bhi, Blo, m0, n0);

    for (int it = 0; it < NK; ++it) {
        asm volatile("cp.async.wait_group 0;" ::: "memory");
        __syncthreads();
        if (it + 1 < NK) load_stage<K>(sb, tid, it + 1, Ahi, Alo, Bhi, Blo, m0, n0);

        const uint32_t stg = sb + (uint32_t)(it & 1) * STAGE_BYTES;
        const uint32_t sAh = stg, sAl = stg + TILE_BYTES;
        const uint32_t sBh = stg + 2 * TILE_BYTES, sBl = stg + 3 * TILE_BYTES;

#pragma unroll
        for (int ks = 0; ks < 4; ks++) {
            const uint32_t bc = (uint32_t)(ks * 32 + colpart);
            unsigned ah[4][4], al[4][4], bh[2][4], bl[2][4];
#pragma unroll
            for (int mt = 0; mt < 4; mt++) {
                uint32_t off = aBase[mt] + (bc ^ aXor[mt]);
                ldm4(ah[mt], sAh + off);
                ldm4(al[mt], sAl + off);
            }
#pragma unroll
            for (int np = 0; np < 2; np++) {
                uint32_t off = bBase[np] + (bc ^ bXor[np]);
                ldm4(bh[np], sBh + off);
                ldm4(bl[np], sBl + off);
            }
#pragma unroll
            for (int mt = 0; mt < 4; mt++) {
#pragma unroll
                for (int nt = 0; nt < 4; nt++) {
                    const int np = nt >> 1, w = nt & 1;
                    mma16816(acc[mt][nt], ah[mt], bh[np][w], bh[np][w + 2]);  // hi*hi
                    mma16816(acc[mt][nt], ah[mt], bl[np][w], bl[np][w + 2]);  // hi*lo
                    mma16816(acc[mt][nt], al[mt], bh[np][w], bh[np][w + 2]);  // lo*hi
                }
            }
        }
    }

    // -------- epilogue --------
    const int group = lane >> 2, tig = lane & 3;
#pragma unroll
    for (int mt = 0; mt < 4; mt++) {
        int r0 = m0 + wm + mt * 16 + group;
#pragma unroll
        for (int nt = 0; nt < 4; nt++) {
            int c = n0 + wn + nt * 8 + tig * 2;
            float v0 = acc[mt][nt][0], v1 = acc[mt][nt][1];
            float v2 = acc[mt][nt][2], v3 = acc[mt][nt][3];
            if (MODE == 0) {
                float bb0 = bias[e * HH + c], bb1 = bias[e * HH + c + 1];
                v0 = fmaxf(v0 + bb0, 0.f);
                v1 = fmaxf(v1 + bb1, 0.f);
                v2 = fmaxf(v2 + bb0, 0.f);
                v3 = fmaxf(v3 + bb1, 0.f);
                __nv_bfloat16 h0, h1, h2, h3, l0, l1, l2, l3;
                split2(v0, h0, l0); split2(v1, h1, l1);
                split2(v2, h2, l2); split2(v3, h3, l3);
                size_t base = (size_t)b * TT * HH;
                size_t i0 = base + (size_t)r0 * HH + c;
                size_t i8 = base + (size_t)(r0 + 8) * HH + c;
                *(__nv_bfloat162*)&g_hhi[i0] = __halves2bfloat162(h0, h1);
                *(__nv_bfloat162*)&g_hlo[i0] = __halves2bfloat162(l0, l1);
                *(__nv_bfloat162*)&g_hhi[i8] = __halves2bfloat162(h2, h3);
                *(__nv_bfloat162*)&g_hlo[i8] = __halves2bfloat162(l2, l3);
            } else {
                float bb0 = bias[e * DD + c], bb1 = bias[e * DD + c + 1];
                size_t base = (size_t)b * TT * DD;
                float2 p0 = make_float2(v0 + bb0, v1 + bb1);
                float2 p1 = make_float2(v2 + bb0, v3 + bb1);
                *(float2*)&out[base + (size_t)r0 * DD + c] = p0;
                *(float2*)&out[base + (size_t)(r0 + 8) * DD + c] = p1;
            }
        }
    }
}

// ---------------- launch ----------------
extern "C" void kernel_launch(void* const* d_in, const int* in_sizes, int n_in,
                              void* d_out, int out_size) {
    const float* x  = (const float*)d_in[0];
    const float* Wp = (const float*)d_in[1];
    const float* bp = (const float*)d_in[2];
    const float* W1 = (const float*)d_in[3];
    const float* b1 = (const float*)d_in[4];
    const float* W2 = (const float*)d_in[5];
    const float* b2 = (const float*)d_in[6];
    float* out = (float*)d_out;
    (void)in_sizes; (void)n_in;

    cudaFuncSetAttribute((const void*)ffn_gemm<0>,
                         cudaFuncAttributeMaxDynamicSharedMemorySize, SMEM_BYTES);
    cudaFuncSetAttribute((const void*)ffn_gemm<1>,
                         cudaFuncAttributeMaxDynamicSharedMemorySize, SMEM_BYTES);

    xsplit_kernel<<<2048, 256>>>(x);
    // W1: [E][D=512][H=2048] -> [E][H][D]
    tsplit_kernel<<<dim3(HH / 32, DD / 32, EE), dim3(32, 8)>>>(W1, 0, DD, HH);
    // W2: [E][H=2048][D=512] -> [E][D][H]
    tsplit_kernel<<<dim3(DD / 32, HH / 32, EE), dim3(32, 8)>>>(W2, 1, HH, DD);
    pool_kernel<<<dim3(BB, 4), DD>>>(x);
    router_kernel<<<1, 256>>>(Wp, bp, out, out_size);

    // GEMM1: per-batch [512 x 2048], K=512
    ffn_gemm<0><<<dim3(HH / TN, TT / TM, BB), 256, SMEM_BYTES>>>(b1, out);
    // GEMM2: per-batch [512 x 512], K=2048
    ffn_gemm<1><<<dim3(DD / TN, TT / TM, BB), 256, SMEM_BYTES>>>(b2, out);
}

// round 11
// speedup vs baseline: 2.5218x; 1.6029x over previous
#include <cuda_runtime.h>
#include <cuda_fp16.h>
#include <cstdint>

// Problem dims
#define BB 32
#define TT 512
#define DD 512
#define EE 8
#define HH 2048

// GEMM tile config
#define TM 128
#define TN 128
#define BK 64   // K per smem stage (128B rows -> SW128 swizzle)

// ---------------- device scratch (no allocations allowed) ----------------
__device__ __half g_xhi[(size_t)BB*TT*DD];
__device__ __half g_xlo[(size_t)BB*TT*DD];
__device__ __half g_w1t[(size_t)EE*HH*DD];  // transposed: [E][H][D], single fp16
__device__ __half g_w2t[(size_t)EE*DD*HH];  // transposed: [E][D][H], single fp16
__device__ __half g_hhi[(size_t)BB*TT*HH];
__device__ __half g_hlo[(size_t)BB*TT*HH];
__device__ float g_pool_part[BB*4*DD];
__device__ int   g_chosen_d[BB];

// ---------------- helpers ----------------
__device__ __forceinline__ void split2h(float v, __half& hi, __half& lo) {
    hi = __float2half_rn(v);
    lo = __float2half_rn(v - __half2float(hi));
}
__device__ __forceinline__ uint32_t s2u(const void* p) {
    uint32_t a;
    asm("{ .reg .u64 t; cvta.to.shared.u64 t, %1; cvt.u32.u64 %0, t; }" : "=r"(a) : "l"(p));
    return a;
}
__device__ __forceinline__ void cp16(uint32_t dst, const void* src) {
    asm volatile("cp.async.cg.shared.global [%0], [%1], 16;" :: "r"(dst), "l"(src));
}
__device__ __forceinline__ void mma16816(float c[4], const unsigned a[4],
                                         unsigned b0, unsigned b1) {
    asm volatile(
        "mma.sync.aligned.m16n8k16.row.col.f32.f16.f16.f32 "
        "{%0,%1,%2,%3},{%4,%5,%6,%7},{%8,%9},{%0,%1,%2,%3};\n"
        : "+f"(c[0]), "+f"(c[1]), "+f"(c[2]), "+f"(c[3])
        : "r"(a[0]), "r"(a[1]), "r"(a[2]), "r"(a[3]), "r"(b0), "r"(b1));
}
__device__ __forceinline__ void ldm4(unsigned r[4], uint32_t a) {
    asm volatile("ldmatrix.sync.aligned.m8n8.x4.shared.b16 {%0,%1,%2,%3}, [%4];"
                 : "=r"(r[0]), "=r"(r[1]), "=r"(r[2]), "=r"(r[3]) : "r"(a));
}

// ---------------- fused split-x + pooling: one pass over x ----------------
__global__ void xsplit_pool_kernel(const float* __restrict__ x) {
    int b = blockIdx.x, s = blockIdx.y, d = threadIdx.x;  // 512 threads
    size_t base = ((size_t)b * TT + (size_t)s * 128) * DD + d;
    float acc = 0.f;
#pragma unroll 8
    for (int t = 0; t < 128; t++) {
        float v = x[base + (size_t)t * DD];
        acc += v;
        __half h, l;
        split2h(v, h, l);
        g_xhi[base + (size_t)t * DD] = h;
        g_xlo[base + (size_t)t * DD] = l;
    }
    g_pool_part[(b * 4 + s) * DD + d] = acc;
}

// ---------------- transpose + convert weights: [E][R][C] fp32 -> [E][C][R] fp16 ----
__global__ void tsplit_kernel(const float* __restrict__ in, int which, int R, int C) {
    __shared__ float t[32][33];
    __half* H = (which ? g_w2t : g_w1t) + (size_t)blockIdx.z * R * C;
    const float* src = in + (size_t)blockIdx.z * R * C;
    int c0 = blockIdx.x * 32, r0 = blockIdx.y * 32;
    int tx = threadIdx.x, ty = threadIdx.y;  // block (32, 8)
#pragma unroll
    for (int i = ty; i < 32; i += 8)
        t[i][tx] = src[(size_t)(r0 + i) * C + c0 + tx];
    __syncthreads();
#pragma unroll
    for (int i = ty; i < 32; i += 8)
        H[(size_t)(c0 + i) * R + r0 + tx] = __float2half_rn(t[tx][i]);
}

// ---------------- router: warp per utterance ----------------
__global__ void router_kernel(const float* __restrict__ Wp, const float* __restrict__ bp,
                              float* __restrict__ out, int out_size) {
    int b = threadIdx.x >> 5, lane = threadIdx.x & 31;  // 1024 threads = 32 warps
    const float* P = g_pool_part + (size_t)b * 4 * DD;
    float acc[EE];
#pragma unroll
    for (int e = 0; e < EE; e++) acc[e] = 0.f;
    for (int d = lane; d < DD; d += 32) {
        float p = (P[d] + P[DD + d] + P[2 * DD + d] + P[3 * DD + d]) * (1.f / (float)TT);
#pragma unroll
        for (int e = 0; e < EE; e++) acc[e] += p * Wp[d * EE + e];
    }
#pragma unroll
    for (int e = 0; e < EE; e++)
#pragma unroll
        for (int off = 16; off; off >>= 1)
            acc[e] += __shfl_xor_sync(0xFFFFFFFFu, acc[e], off);
    if (lane == 0) {
        float mx = -1e30f;
        int arg = 0;
#pragma unroll
        for (int e = 0; e < EE; e++) {
            acc[e] += bp[e];
            if (acc[e] > mx) { mx = acc[e]; arg = e; }
        }
        float sum = 0.f, ex[EE];
#pragma unroll
        for (int e = 0; e < EE; e++) { ex[e] = expf(acc[e] - mx); sum += ex[e]; }
        g_chosen_d[b] = arg;
        if (out_size >= BB * TT * DD + BB * EE + BB) {
            float inv = 1.f / sum;
#pragma unroll
            for (int e = 0; e < EE; e++) out[BB * TT * DD + b * EE + e] = ex[e] * inv;
            out[BB * TT * DD + BB * EE + b] = (float)arg;
        }
    }
}

// ---------------- pipelined HMMA GEMM (fp16: A hi/lo x2 MMA passes, fp32 accum) ----
// smem: 2 stages x 3 tiles (Ahi, Alo, B), each tile 128 rows x 128B, SW128.
#define TILE_BYTES  16384
#define STAGE_BYTES (3 * TILE_BYTES)
#define SMEM_BYTES  (2 * STAGE_BYTES)

template <int K>
__device__ __forceinline__ void load_stage(uint32_t sb, int tid, int it,
                                           const __half* Ahi, const __half* Alo,
                                           const __half* Bt, int m0, int n0) {
    int s = it & 1, k0 = it * BK;
    const __half* srcs[3] = {Ahi + (size_t)m0 * K, Alo + (size_t)m0 * K,
                             Bt + (size_t)n0 * K};
#pragma unroll
    for (int t = 0; t < 3; t++) {
        uint32_t base = sb + (uint32_t)s * STAGE_BYTES + (uint32_t)t * TILE_BYTES;
        const char* g = (const char*)srcs[t] + (size_t)k0 * 2;
#pragma unroll
        for (int i = 0; i < 4; i++) {
            int idx = tid + i * 256;          // 1024 chunks of 16B per tile
            int r = idx >> 3, c = idx & 7;
            uint32_t off = (uint32_t)(r * 128 + c * 16);
            cp16(base + (off ^ ((off >> 3) & 0x70)), g + (size_t)r * (K * 2) + c * 16);
        }
    }
    asm volatile("cp.async.commit_group;" ::: "memory");
}

// MODE 0: h = relu(x @ W1t^T + b1)  [M=512, N=2048, K=512]  -> fp16 hi/lo scratch
// MODE 1: out = h @ W2t^T + b2      [M=512, N=512,  K=2048] -> fp32 d_out
template <int MODE>
__global__ void __launch_bounds__(256) ffn_gemm(const float* __restrict__ bias,
                                                float* __restrict__ out) {
    constexpr int K = (MODE == 0) ? DD : HH;
    constexpr int NK = K / BK;
    extern __shared__ char smem[];
    uint32_t sb = s2u(smem);
    const int tid = threadIdx.x, wid = tid >> 5, lane = tid & 31;
    const int b = blockIdx.z, m0 = blockIdx.y * TM, n0 = blockIdx.x * TN;
    const int e = g_chosen_d[b];
    const int wm = (wid >> 2) * 64;   // 2 warps along M
    const int wn = (wid & 3) * 32;    // 4 warps along N

    const __half *Ahi, *Alo, *Bt;
    if (MODE == 0) {
        Ahi = g_xhi + (size_t)b * TT * DD;  Alo = g_xlo + (size_t)b * TT * DD;
        Bt  = g_w1t + (size_t)e * HH * DD;
    } else {
        Ahi = g_hhi + (size_t)b * TT * HH;  Alo = g_hlo + (size_t)b * TT * HH;
        Bt  = g_w2t + (size_t)e * DD * HH;
    }

    // per-thread ldmatrix addressing (row fixed per tile; only k-offset varies)
    const int colpart = (lane >> 4) << 4;      // 0 or 16 bytes (k8..15 half)
    uint32_t aBase[4], aXor[4], bBase[2], bXor[2];
#pragma unroll
    for (int mt = 0; mt < 4; mt++) {
        int r = wm + mt * 16 + (lane & 15);
        aBase[mt] = (uint32_t)(r * 128);
        aXor[mt]  = (uint32_t)((r & 7) << 4);
    }
#pragma unroll
    for (int np = 0; np < 2; np++) {
        int r = wn + np * 16 + (lane & 15);
        bBase[np] = (uint32_t)(r * 128);
        bXor[np]  = (uint32_t)((r & 7) << 4);
    }

    float acc[4][4][4];
#pragma unroll
    for (int mt = 0; mt < 4; mt++)
#pragma unroll
        for (int nt = 0; nt < 4; nt++)
#pragma unroll
            for (int i = 0; i < 4; i++) acc[mt][nt][i] = 0.f;

    load_stage<K>(sb, tid, 0, Ahi, Alo, Bt, m0, n0);

    for (int it = 0; it < NK; ++it) {
        asm volatile("cp.async.wait_group 0;" ::: "memory");
        __syncthreads();
        if (it + 1 < NK) load_stage<K>(sb, tid, it + 1, Ahi, Alo, Bt, m0, n0);

        const uint32_t stg = sb + (uint32_t)(it & 1) * STAGE_BYTES;
        const uint32_t sAh = stg, sAl = stg + TILE_BYTES, sB = stg + 2 * TILE_BYTES;

#pragma unroll
        for (int ks = 0; ks < 4; ks++) {
            const uint32_t bc = (uint32_t)(ks * 32 + colpart);
            unsigned ah[4][4], al[4][4], bh[2][4];
#pragma unroll
            for (int mt = 0; mt < 4; mt++) {
                uint32_t off = aBase[mt] + (bc ^ aXor[mt]);
                ldm4(ah[mt], sAh + off);
                ldm4(al[mt], sAl + off);
            }
#pragma unroll
            for (int np = 0; np < 2; np++) {
                uint32_t off = bBase[np] + (bc ^ bXor[np]);
                ldm4(bh[np], sB + off);
            }
#pragma unroll
            for (int mt = 0; mt < 4; mt++) {
#pragma unroll
                for (int nt = 0; nt < 4; nt++) {
                    const int np = nt >> 1, w = nt & 1;
                    mma16816(acc[mt][nt], ah[mt], bh[np][w], bh[np][w + 2]);  // ahi * b
                    mma16816(acc[mt][nt], al[mt], bh[np][w], bh[np][w + 2]);  // alo * b
                }
            }
        }
    }

    // -------- epilogue --------
    const int group = lane >> 2, tig = lane & 3;
#pragma unroll
    for (int mt = 0; mt < 4; mt++) {
        int r0 = m0 + wm + mt * 16 + group;
#pragma unroll
        for (int nt = 0; nt < 4; nt++) {
            int c = n0 + wn + nt * 8 + tig * 2;
            float v0 = acc[mt][nt][0], v1 = acc[mt][nt][1];
            float v2 = acc[mt][nt][2], v3 = acc[mt][nt][3];
            if (MODE == 0) {
                float bb0 = bias[e * HH + c], bb1 = bias[e * HH + c + 1];
                v0 = fmaxf(v0 + bb0, 0.f);
                v1 = fmaxf(v1 + bb1, 0.f);
                v2 = fmaxf(v2 + bb0, 0.f);
                v3 = fmaxf(v3 + bb1, 0.f);
                __half h0, h1, h2, h3, l0, l1, l2, l3;
                split2h(v0, h0, l0); split2h(v1, h1, l1);
                split2h(v2, h2, l2); split2h(v3, h3, l3);
                size_t base = (size_t)b * TT * HH;
                size_t i0 = base + (size_t)r0 * HH + c;
                size_t i8 = base + (size_t)(r0 + 8) * HH + c;
                *(__half2*)&g_hhi[i0] = __halves2half2(h0, h1);
                *(__half2*)&g_hlo[i0] = __halves2half2(l0, l1);
                *(__half2*)&g_hhi[i8] = __halves2half2(h2, h3);
                *(__half2*)&g_hlo[i8] = __halves2half2(l2, l3);
            } else {
                float bb0 = bias[e * DD + c], bb1 = bias[e * DD + c + 1];
                size_t base = (size_t)b * TT * DD;
                float2 p0 = make_float2(v0 + bb0, v1 + bb1);
                float2 p1 = make_float2(v2 + bb0, v3 + bb1);
                *(float2*)&out[base + (size_t)r0 * DD + c] = p0;
                *(float2*)&out[base + (size_t)(r0 + 8) * DD + c] = p1;
            }
        }
    }
}

// ---------------- launch ----------------
extern "C" void kernel_launch(void* const* d_in, const int* in_sizes, int n_in,
                              void* d_out, int out_size) {
    const float* x  = (const float*)d_in[0];
    const float* Wp = (const float*)d_in[1];
    const float* bp = (const float*)d_in[2];
    const float* W1 = (const float*)d_in[3];
    const float* b1 = (const float*)d_in[4];
    const float* W2 = (const float*)d_in[5];
    const float* b2 = (const float*)d_in[6];
    float* out = (float*)d_out;
    (void)in_sizes; (void)n_in;

    cudaFuncSetAttribute((const void*)ffn_gemm<0>,
                         cudaFuncAttributeMaxDynamicSharedMemorySize, SMEM_BYTES);
    cudaFuncSetAttribute((const void*)ffn_gemm<1>,
                         cudaFuncAttributeMaxDynamicSharedMemorySize, SMEM_BYTES);

    xsplit_pool_kernel<<<dim3(BB, 4), DD>>>(x);
    // W1: [E][D=512][H=2048] -> [E][H][D]
    tsplit_kernel<<<dim3(HH / 32, DD / 32, EE), dim3(32, 8)>>>(W1, 0, DD, HH);
    // W2: [E][H=2048][D=512] -> [E][D][H]
    tsplit_kernel<<<dim3(DD / 32, HH / 32, EE), dim3(32, 8)>>>(W2, 1, HH, DD);
    router_kernel<<<1, 1024>>>(Wp, bp, out, out_size);

    // GEMM1: per-batch [512 x 2048], K=512
    ffn_gemm<0><<<dim3(HH / TN, TT / TM, BB), 256, SMEM_BYTES>>>(b1, out);
    // GEMM2: per-batch [512 x 512], K=2048
    ffn_gemm<1><<<dim3(DD / TN, TT / TM, BB), 256, SMEM_BYTES>>>(b2, out);
}

// round 16
// speedup vs baseline: 4.4174x; 1.7517x over previous
#include <cuda_runtime.h>
#include <cuda_fp16.h>
#include <cstdint>

// Problem dims
#define BB 32
#define TT 512
#define DD 512
#define EE 8
#define HH 2048

// GEMM tile config
#define TM 128
#define TN 128
#define BK 64   // K per smem stage (128B rows -> SW128 swizzle)

// ---------------- device scratch (no allocations allowed) ----------------
__device__ __half g_xh[(size_t)BB*TT*DD];
__device__ __half g_w1t[(size_t)EE*HH*DD];  // transposed: [E][H][D], fp16
__device__ __half g_w2t[(size_t)EE*DD*HH];  // transposed: [E][D][H], fp16
__device__ __half g_hh[(size_t)BB*TT*HH];
__device__ float g_pool_part[BB*4*DD];
__device__ int   g_chosen_d[BB];

// ---------------- helpers ----------------
__device__ __forceinline__ uint32_t s2u(const void* p) {
    uint32_t a;
    asm("{ .reg .u64 t; cvta.to.shared.u64 t, %1; cvt.u32.u64 %0, t; }" : "=r"(a) : "l"(p));
    return a;
}
__device__ __forceinline__ void cp16(uint32_t dst, const void* src) {
    asm volatile("cp.async.cg.shared.global [%0], [%1], 16;" :: "r"(dst), "l"(src));
}
__device__ __forceinline__ void mma16816(float c[4], const unsigned a[4],
                                         unsigned b0, unsigned b1) {
    asm volatile(
        "mma.sync.aligned.m16n8k16.row.col.f32.f16.f16.f32 "
        "{%0,%1,%2,%3},{%4,%5,%6,%7},{%8,%9},{%0,%1,%2,%3};\n"
        : "+f"(c[0]), "+f"(c[1]), "+f"(c[2]), "+f"(c[3])
        : "r"(a[0]), "r"(a[1]), "r"(a[2]), "r"(a[3]), "r"(b0), "r"(b1));
}
__device__ __forceinline__ void ldm4(unsigned r[4], uint32_t a) {
    asm volatile("ldmatrix.sync.aligned.m8n8.x4.shared.b16 {%0,%1,%2,%3}, [%4];"
                 : "=r"(r[0]), "=r"(r[1]), "=r"(r[2]), "=r"(r[3]) : "r"(a));
}

// ---------------- fused x->fp16 convert + pooling: one pass over x ----------------
__global__ void xsplit_pool_kernel(const float* __restrict__ x) {
    int b = blockIdx.x, s = blockIdx.y, d = threadIdx.x;  // 512 threads
    size_t base = ((size_t)b * TT + (size_t)s * 128) * DD + d;
    float acc = 0.f;
#pragma unroll 8
    for (int t = 0; t < 128; t++) {
        float v = x[base + (size_t)t * DD];
        acc += v;
        g_xh[base + (size_t)t * DD] = __float2half_rn(v);
    }
    g_pool_part[(b * 4 + s) * DD + d] = acc;
}

// ---------------- transpose + convert weights: [E][R][C] fp32 -> [E][C][R] fp16 ----
__global__ void tsplit_kernel(const float* __restrict__ in, int which, int R, int C) {
    __shared__ float t[32][33];
    __half* H = (which ? g_w2t : g_w1t) + (size_t)blockIdx.z * R * C;
    const float* src = in + (size_t)blockIdx.z * R * C;
    int c0 = blockIdx.x * 32, r0 = blockIdx.y * 32;
    int tx = threadIdx.x, ty = threadIdx.y;  // block (32, 8)
#pragma unroll
    for (int i = ty; i < 32; i += 8)
        t[i][tx] = src[(size_t)(r0 + i) * C + c0 + tx];
    __syncthreads();
#pragma unroll
    for (int i = ty; i < 32; i += 8)
        H[(size_t)(c0 + i) * R + r0 + tx] = __float2half_rn(t[tx][i]);
}

// ---------------- router: one block per utterance, 256 threads ----------------
__global__ void router_kernel(const float* __restrict__ Wp, const float* __restrict__ bp,
                              float* __restrict__ out, int out_size) {
    __shared__ float red[8][EE];
    int b = blockIdx.x, tid = threadIdx.x;
    int warp = tid >> 5, lane = tid & 31;
    const float* P = g_pool_part + (size_t)b * 4 * DD;
    float acc[EE];
#pragma unroll
    for (int e = 0; e < EE; e++) acc[e] = 0.f;
#pragma unroll
    for (int d = tid; d < DD; d += 256) {
        float p = (P[d] + P[DD + d] + P[2 * DD + d] + P[3 * DD + d]) * (1.f / (float)TT);
        float4 w0 = *(const float4*)&Wp[d * EE];
        float4 w1 = *(const float4*)&Wp[d * EE + 4];
        acc[0] += p * w0.x; acc[1] += p * w0.y; acc[2] += p * w0.z; acc[3] += p * w0.w;
        acc[4] += p * w1.x; acc[5] += p * w1.y; acc[6] += p * w1.z; acc[7] += p * w1.w;
    }
#pragma unroll
    for (int e = 0; e < EE; e++)
#pragma unroll
        for (int off = 16; off; off >>= 1)
            acc[e] += __shfl_xor_sync(0xFFFFFFFFu, acc[e], off);
    if (lane == 0)
#pragma unroll
        for (int e = 0; e < EE; e++) red[warp][e] = acc[e];
    __syncthreads();
    if (tid == 0) {
        float lg[EE];
        float mx = -1e30f;
        int arg = 0;
#pragma unroll
        for (int e = 0; e < EE; e++) {
            float v = bp[e];
#pragma unroll
            for (int w = 0; w < 8; w++) v += red[w][e];
            lg[e] = v;
            if (v > mx) { mx = v; arg = e; }
        }
        float sum = 0.f, ex[EE];
#pragma unroll
        for (int e = 0; e < EE; e++) { ex[e] = expf(lg[e] - mx); sum += ex[e]; }
        g_chosen_d[b] = arg;
        if (out_size >= BB * TT * DD + BB * EE + BB) {
            float inv = 1.f / sum;
#pragma unroll
            for (int e = 0; e < EE; e++) out[BB * TT * DD + b * EE + e] = ex[e] * inv;
            out[BB * TT * DD + BB * EE + b] = (float)arg;
        }
    }
}

// ---------------- 3-stage pipelined HMMA GEMM (fp16, single pass, fp32 accum) ----
// smem: 3 stages x 2 tiles (A, B), each tile 128 rows x 128B, SW128 swizzled.
#define TILE_BYTES  16384
#define STAGE_BYTES (2 * TILE_BYTES)
#define SMEM_BYTES  (3 * STAGE_BYTES)

template <int K>
__device__ __forceinline__ void load_stage(uint32_t sb, int tid, int it,
                                           const __half* A, const __half* Bt,
                                           int m0, int n0) {
    int s = it % 3, k0 = it * BK;
    const __half* srcs[2] = {A + (size_t)m0 * K, Bt + (size_t)n0 * K};
#pragma unroll
    for (int t = 0; t < 2; t++) {
        uint32_t base = sb + (uint32_t)s * STAGE_BYTES + (uint32_t)t * TILE_BYTES;
        const char* g = (const char*)srcs[t] + (size_t)k0 * 2;
#pragma unroll
        for (int i = 0; i < 4; i++) {
            int idx = tid + i * 256;          // 1024 chunks of 16B per tile
            int r = idx >> 3, c = idx & 7;
            uint32_t off = (uint32_t)(r * 128 + c * 16);
            cp16(base + (off ^ ((off >> 3) & 0x70)), g + (size_t)r * (K * 2) + c * 16);
        }
    }
    asm volatile("cp.async.commit_group;" ::: "memory");
}

// MODE 0: h = relu(x @ W1t^T + b1)  [M=512, N=2048, K=512]  -> fp16 scratch
// MODE 1: out = h @ W2t^T + b2      [M=512, N=512,  K=2048] -> fp32 d_out
template <int MODE>
__global__ void __launch_bounds__(256) ffn_gemm(const float* __restrict__ bias,
                                                float* __restrict__ out) {
    constexpr int K = (MODE == 0) ? DD : HH;
    constexpr int NK = K / BK;
    extern __shared__ char smem[];
    uint32_t sb = s2u(smem);
    const int tid = threadIdx.x, wid = tid >> 5, lane = tid & 31;
    const int b = blockIdx.z, m0 = blockIdx.y * TM, n0 = blockIdx.x * TN;
    const int e = g_chosen_d[b];
    const int wm = (wid >> 2) * 64;   // 2 warps along M
    const int wn = (wid & 3) * 32;    // 4 warps along N

    const __half *A, *Bt;
    if (MODE == 0) {
        A  = g_xh + (size_t)b * TT * DD;
        Bt = g_w1t + (size_t)e * HH * DD;
    } else {
        A  = g_hh + (size_t)b * TT * HH;
        Bt = g_w2t + (size_t)e * DD * HH;
    }

    // per-thread ldmatrix addressing (row fixed per tile; only k-offset varies)
    const int colpart = (lane >> 4) << 4;      // 0 or 16 bytes (k8..15 half)
    uint32_t aBase[4], aXor[4], bBase[2], bXor[2];
#pragma unroll
    for (int mt = 0; mt < 4; mt++) {
        int r = wm + mt * 16 + (lane & 15);
        aBase[mt] = (uint32_t)(r * 128);
        aXor[mt]  = (uint32_t)((r & 7) << 4);
    }
#pragma unroll
    for (int np = 0; np < 2; np++) {
        int r = wn + np * 16 + (lane & 15);
        bBase[np] = (uint32_t)(r * 128);
        bXor[np]  = (uint32_t)((r & 7) << 4);
    }

    float acc[4][4][4];
#pragma unroll
    for (int mt = 0; mt < 4; mt++)
#pragma unroll
        for (int nt = 0; nt < 4; nt++)
#pragma unroll
            for (int i = 0; i < 4; i++) acc[mt][nt][i] = 0.f;

    load_stage<K>(sb, tid, 0, A, Bt, m0, n0);
    load_stage<K>(sb, tid, 1, A, Bt, m0, n0);

    for (int it = 0; it < NK; ++it) {
        if (it + 2 < NK) {
            asm volatile("cp.async.wait_group 1;" ::: "memory");
        } else {
            asm volatile("cp.async.wait_group 0;" ::: "memory");
        }
        __syncthreads();

        const uint32_t stg = sb + (uint32_t)(it % 3) * STAGE_BYTES;
        const uint32_t sA = stg, sB = stg + TILE_BYTES;

#pragma unroll
        for (int ks = 0; ks < 4; ks++) {
            const uint32_t bc = (uint32_t)(ks * 32 + colpart);
            unsigned ah[4][4], bh[2][4];
#pragma unroll
            for (int mt = 0; mt < 4; mt++)
                ldm4(ah[mt], sA + aBase[mt] + (bc ^ aXor[mt]));
#pragma unroll
            for (int np = 0; np < 2; np++)
                ldm4(bh[np], sB + bBase[np] + (bc ^ bXor[np]));
#pragma unroll
            for (int mt = 0; mt < 4; mt++) {
#pragma unroll
                for (int nt = 0; nt < 4; nt++) {
                    const int np = nt >> 1, w = nt & 1;
                    mma16816(acc[mt][nt], ah[mt], bh[np][w], bh[np][w + 2]);
                }
            }
        }
        if (it + 2 < NK) load_stage<K>(sb, tid, it + 2, A, Bt, m0, n0);
    }

    // -------- epilogue --------
    const int group = lane >> 2, tig = lane & 3;
#pragma unroll
    for (int mt = 0; mt < 4; mt++) {
        int r0 = m0 + wm + mt * 16 + group;
#pragma unroll
        for (int nt = 0; nt < 4; nt++) {
            int c = n0 + wn + nt * 8 + tig * 2;
            float v0 = acc[mt][nt][0], v1 = acc[mt][nt][1];
            float v2 = acc[mt][nt][2], v3 = acc[mt][nt][3];
            if (MODE == 0) {
                float bb0 = bias[e * HH + c], bb1 = bias[e * HH + c + 1];
                v0 = fmaxf(v0 + bb0, 0.f);
                v1 = fmaxf(v1 + bb1, 0.f);
                v2 = fmaxf(v2 + bb0, 0.f);
                v3 = fmaxf(v3 + bb1, 0.f);
                size_t base = (size_t)b * TT * HH;
                size_t i0 = base + (size_t)r0 * HH + c;
                size_t i8 = base + (size_t)(r0 + 8) * HH + c;
                *(__half2*)&g_hh[i0] = __halves2half2(__float2half_rn(v0), __float2half_rn(v1));
                *(__half2*)&g_hh[i8] = __halves2half2(__float2half_rn(v2), __float2half_rn(v3));
            } else {
                float bb0 = bias[e * DD + c], bb1 = bias[e * DD + c + 1];
                size_t base = (size_t)b * TT * DD;
                float2 p0 = make_float2(v0 + bb0, v1 + bb1);
                float2 p1 = make_float2(v2 + bb0, v3 + bb1);
                *(float2*)&out[base + (size_t)r0 * DD + c] = p0;
                *(float2*)&out[base + (size_t)(r0 + 8) * DD + c] = p1;
            }
        }
    }
}

// ---------------- launch ----------------
extern "C" void kernel_launch(void* const* d_in, const int* in_sizes, int n_in,
                              void* d_out, int out_size) {
    const float* x  = (const float*)d_in[0];
    const float* Wp = (const float*)d_in[1];
    const float* bp = (const float*)d_in[2];
    const float* W1 = (const float*)d_in[3];
    const float* b1 = (const float*)d_in[4];
    const float* W2 = (const float*)d_in[5];
    const float* b2 = (const float*)d_in[6];
    float* out = (float*)d_out;
    (void)in_sizes; (void)n_in;

    cudaFuncSetAttribute((const void*)ffn_gemm<0>,
                         cudaFuncAttributeMaxDynamicSharedMemorySize, SMEM_BYTES);
    cudaFuncSetAttribute((const void*)ffn_gemm<1>,
                         cudaFuncAttributeMaxDynamicSharedMemorySize, SMEM_BYTES);

    xsplit_pool_kernel<<<dim3(BB, 4), DD>>>(x);
    // W1: [E][D=512][H=2048] -> [E][H][D]
    tsplit_kernel<<<dim3(HH / 32, DD / 32, EE), dim3(32, 8)>>>(W1, 0, DD, HH);
    // W2: [E][H=2048][D=512] -> [E][D][H]
    tsplit_kernel<<<dim3(DD / 32, HH / 32, EE), dim3(32, 8)>>>(W2, 1, HH, DD);
    router_kernel<<<BB, 256>>>(Wp, bp, out, out_size);

    // GEMM1: per-batch [512 x 2048], K=512
    ffn_gemm<0><<<dim3(HH / TN, TT / TM, BB), 256, SMEM_BYTES>>>(b1, out);
    // GEMM2: per-batch [512 x 512], K=2048
    ffn_gemm<1><<<dim3(DD / TN, TT / TM, BB), 256, SMEM_BYTES>>>(b2, out);
}